// round 1
// baseline (speedup 1.0000x reference)
#include <cuda_runtime.h>
#include <cuda_bf16.h>

// Problem constants
static constexpr int B  = 2;
static constexpr int S  = 2048;
static constexpr int D  = 1024;
static constexpr int H  = 16;
static constexpr int DK = 64;

// Scratch (device globals: allocation-free rule)
__device__ float g_Q[B * S * D];
__device__ float g_K[B * S * D];
__device__ float g_V[B * S * D];
__device__ float g_C[B * S * D];

// ---------------------------------------------------------------------------
// SGEMM: C[M,N] = A[M,K] @ W[N,K]^T   (both operands K-contiguous, row-major)
// 64x64 block tile, BK=16, 256 threads, 4x4 register micro-tile.
// ---------------------------------------------------------------------------
__global__ __launch_bounds__(256)
void sgemm_nt(const float* __restrict__ A, const float* __restrict__ W,
              float* __restrict__ C, int M, int N, int K) {
    __shared__ float As[16][68];   // [k][row], pad 68 keeps 16B alignment
    __shared__ float Ws[16][68];   // [k][col]

    const int tid = threadIdx.x;
    const int ty  = tid >> 4;      // 0..15
    const int tx  = tid & 15;      // 0..15
    const int by  = blockIdx.y;
    const int bx  = blockIdx.x;

    // cooperative load mapping: each thread loads one float4 of A and W per k-tile
    const int lr  = tid >> 2;          // 0..63  (tile row)
    const int lc4 = (tid & 3) << 2;    // 0,4,8,12 (k offset)

    const float* Ag = A + (size_t)(by * 64 + lr) * K;
    const float* Wg = W + (size_t)(bx * 64 + lr) * K;

    float acc[4][4] = {};

    for (int kt = 0; kt < K; kt += 16) {
        float4 av = *(const float4*)&Ag[kt + lc4];
        float4 wv = *(const float4*)&Wg[kt + lc4];
        __syncthreads();
        As[lc4 + 0][lr] = av.x; As[lc4 + 1][lr] = av.y;
        As[lc4 + 2][lr] = av.z; As[lc4 + 3][lr] = av.w;
        Ws[lc4 + 0][lr] = wv.x; Ws[lc4 + 1][lr] = wv.y;
        Ws[lc4 + 2][lr] = wv.z; Ws[lc4 + 3][lr] = wv.w;
        __syncthreads();

        #pragma unroll
        for (int k = 0; k < 16; k++) {
            float4 a = *(const float4*)&As[k][ty << 2];
            float4 w = *(const float4*)&Ws[k][tx << 2];
            float ar[4] = {a.x, a.y, a.z, a.w};
            float wr[4] = {w.x, w.y, w.z, w.w};
            #pragma unroll
            for (int i = 0; i < 4; i++)
                #pragma unroll
                for (int j = 0; j < 4; j++)
                    acc[i][j] += ar[i] * wr[j];
        }
    }

    #pragma unroll
    for (int i = 0; i < 4; i++) {
        float4 v = make_float4(acc[i][0], acc[i][1], acc[i][2], acc[i][3]);
        *(float4*)&C[(size_t)(by * 64 + (ty << 2) + i) * N + bx * 64 + (tx << 2)] = v;
    }
}

// ---------------------------------------------------------------------------
// Flash attention (fp32): one query row per thread, 128 rows per block.
// K/V staged in smem tiles of TK=32 keys; tile-level online softmax.
// ctx written directly in [B, S, H*DK] layout.
// ---------------------------------------------------------------------------
static constexpr int TK   = 32;
static constexpr int ROWS = 128;

__global__ __launch_bounds__(ROWS)
void attn_kernel(const float* __restrict__ Q, const float* __restrict__ K,
                 const float* __restrict__ V, float* __restrict__ ctx) {
    __shared__ float Ks[TK][DK];       // 8 KB
    __shared__ float Vs[TK][DK];       // 8 KB
    __shared__ float Ss[TK][ROWS];     // 16 KB, [key][thread] -> conflict-free

    const int b   = blockIdx.z;
    const int h   = blockIdx.y;
    const int qt  = blockIdx.x;
    const int tid = threadIdx.x;
    const int row = qt * ROWS + tid;

    const float* qptr = Q + ((size_t)(b * S + row) * D + h * DK);

    float q[DK], o[DK];
    #pragma unroll
    for (int d = 0; d < DK; d += 4) {
        float4 v = *(const float4*)&qptr[d];
        q[d]     = v.x * 0.125f;   // 1/sqrt(64) folded into q
        q[d + 1] = v.y * 0.125f;
        q[d + 2] = v.z * 0.125f;
        q[d + 3] = v.w * 0.125f;
        o[d] = 0.f; o[d + 1] = 0.f; o[d + 2] = 0.f; o[d + 3] = 0.f;
    }

    float m = -1e30f, l = 0.f;

    const float* Kbase = K + ((size_t)b * S * D + h * DK);
    const float* Vbase = V + ((size_t)b * S * D + h * DK);

    for (int kt = 0; kt < S; kt += TK) {
        __syncthreads();   // protect Ks/Vs from previous iteration's readers
        // cooperative tile load: TK*DK/4 = 512 float4 across 128 threads
        for (int f = tid; f < TK * (DK / 4); f += ROWS) {
            int r  = f / (DK / 4);
            int c4 = (f % (DK / 4)) * 4;
            *(float4*)&Ks[r][c4] = *(const float4*)&Kbase[(size_t)(kt + r) * D + c4];
            *(float4*)&Vs[r][c4] = *(const float4*)&Vbase[(size_t)(kt + r) * D + c4];
        }
        __syncthreads();

        // pass 1: scores + tile max
        float tmax = -1e30f;
        for (int j = 0; j < TK; j++) {
            float s = 0.f;
            #pragma unroll
            for (int d = 0; d < DK; d += 4) {
                float4 kv = *(const float4*)&Ks[j][d];   // broadcast read
                s += q[d] * kv.x + q[d + 1] * kv.y + q[d + 2] * kv.z + q[d + 3] * kv.w;
            }
            Ss[j][tid] = s;
            tmax = fmaxf(tmax, s);
        }

        float mnew  = fmaxf(m, tmax);
        float alpha = __expf(m - mnew);
        l *= alpha;
        #pragma unroll
        for (int d = 0; d < DK; d++) o[d] *= alpha;
        m = mnew;

        // pass 2: exp + PV accumulation
        for (int j = 0; j < TK; j++) {
            float p = __expf(Ss[j][tid] - mnew);
            l += p;
            #pragma unroll
            for (int d = 0; d < DK; d += 4) {
                float4 vv = *(const float4*)&Vs[j][d];   // broadcast read
                o[d]     += p * vv.x;
                o[d + 1] += p * vv.y;
                o[d + 2] += p * vv.z;
                o[d + 3] += p * vv.w;
            }
        }
    }

    const float inv = 1.f / l;
    float* optr = ctx + ((size_t)(b * S + row) * D + h * DK);
    #pragma unroll
    for (int d = 0; d < DK; d += 4) {
        float4 v = make_float4(o[d] * inv, o[d + 1] * inv, o[d + 2] * inv, o[d + 3] * inv);
        *(float4*)&optr[d] = v;
    }
}

// ---------------------------------------------------------------------------
// Launch
// ---------------------------------------------------------------------------
extern "C" void kernel_launch(void* const* d_in, const int* in_sizes, int n_in,
                              void* d_out, int out_size) {
    const float* query = (const float*)d_in[0];
    const float* key   = (const float*)d_in[1];
    const float* value = (const float*)d_in[2];
    const float* w_q   = (const float*)d_in[3];
    const float* w_k   = (const float*)d_in[4];
    const float* w_v   = (const float*)d_in[5];
    const float* w_o   = (const float*)d_in[6];
    float* out = (float*)d_out;

    float *Qp, *Kp, *Vp, *Cp;
    cudaGetSymbolAddress((void**)&Qp, g_Q);
    cudaGetSymbolAddress((void**)&Kp, g_K);
    cudaGetSymbolAddress((void**)&Vp, g_V);
    cudaGetSymbolAddress((void**)&Cp, g_C);

    const int M = B * S;                 // 4096
    dim3 gemm_grid(D / 64, M / 64);      // (16, 64)
    dim3 gemm_block(256);

    sgemm_nt<<<gemm_grid, gemm_block>>>(query, w_q, Qp, M, D, D);
    sgemm_nt<<<gemm_grid, gemm_block>>>(key,   w_k, Kp, M, D, D);
    sgemm_nt<<<gemm_grid, gemm_block>>>(value, w_v, Vp, M, D, D);

    dim3 attn_grid(S / ROWS, H, B);      // (16, 16, 2)
    attn_kernel<<<attn_grid, ROWS>>>(Qp, Kp, Vp, Cp);

    sgemm_nt<<<gemm_grid, gemm_block>>>(Cp, w_o, out, M, D, D);
}

// round 2
// speedup vs baseline: 2.4185x; 2.4185x over previous
#include <cuda_runtime.h>
#include <cstdint>

static constexpr int B  = 2;
static constexpr int S  = 2048;
static constexpr int D  = 1024;
static constexpr int H  = 16;
static constexpr int DK = 64;

// Scratch (device globals: allocation-free rule)
__device__ float g_Q[B * S * D];
__device__ float g_K[B * S * D];
__device__ float g_V[B * S * D];
__device__ float g_C[B * S * D];

// ---------------------------------------------------------------------------
// helpers
// ---------------------------------------------------------------------------
__device__ __forceinline__ unsigned f2tf(float x) {
    unsigned u;
    asm("cvt.rna.tf32.f32 %0, %1;" : "=r"(u) : "f"(x));
    return u;
}
__device__ __forceinline__ float tf32r(float x) { return __uint_as_float(f2tf(x)); }

__device__ __forceinline__ float ex2(float x) {
    float r;
    asm("ex2.approx.f32 %0, %1;" : "=f"(r) : "f"(x));
    return r;
}

__device__ __forceinline__ void mma_tf32(float c[4],
                                         unsigned a0, unsigned a1, unsigned a2, unsigned a3,
                                         unsigned b0, unsigned b1) {
    asm("mma.sync.aligned.m16n8k8.row.col.f32.tf32.tf32.f32 "
        "{%0,%1,%2,%3}, {%4,%5,%6,%7}, {%8,%9}, {%0,%1,%2,%3};"
        : "+f"(c[0]), "+f"(c[1]), "+f"(c[2]), "+f"(c[3])
        : "r"(a0), "r"(a1), "r"(a2), "r"(a3), "r"(b0), "r"(b1));
}

// ---------------------------------------------------------------------------
// 3xTF32 GEMM: C[M,N] = A[M,K] @ W[N,K]^T   (fp32-equivalent accuracy)
// BM=128, BN=128, BK=16, 256 threads, 8 warps (2x4), warp tile 64x32.
// ---------------------------------------------------------------------------
__global__ __launch_bounds__(256)
void gemm_tf32x3(const float* __restrict__ A, const float* __restrict__ W,
                 float* __restrict__ C, int M, int N, int K) {
    __shared__ float Ah[128][20], Al[128][20];
    __shared__ float Wh[128][20], Wl[128][20];

    const int tid  = threadIdx.x;
    const int lane = tid & 31;
    const int warp = tid >> 5;
    const int g    = lane >> 2;   // group 0..7
    const int tg   = lane & 3;    // thread-in-group 0..3
    const int m0   = (warp >> 2) * 64;
    const int n0   = (warp & 3) * 32;
    const int bx   = blockIdx.x, by = blockIdx.y;

    // loader: idx = tid + i*256 -> row = idx>>2, col4 = (idx&3)*4
    const int r0 = tid >> 2;
    const int r1 = r0 + 64;
    const int c4 = (tid & 3) * 4;
    const float* Ag = A + (size_t)(by * 128) * K;
    const float* Wg = W + (size_t)(bx * 128) * K;

    float4 av0 = *(const float4*)&Ag[(size_t)r0 * K + c4];
    float4 av1 = *(const float4*)&Ag[(size_t)r1 * K + c4];
    float4 wv0 = *(const float4*)&Wg[(size_t)r0 * K + c4];
    float4 wv1 = *(const float4*)&Wg[(size_t)r1 * K + c4];

    float acc[4][4][4] = {};

    const int nk = K / 16;
    for (int kt = 0; kt < nk; kt++) {
        __syncthreads();   // prior compute done reading smem
        // split into hi/lo tf32 and store
        {
            float4 v, hi, lo;
            v = av0;
            hi.x = tf32r(v.x); lo.x = tf32r(v.x - hi.x);
            hi.y = tf32r(v.y); lo.y = tf32r(v.y - hi.y);
            hi.z = tf32r(v.z); lo.z = tf32r(v.z - hi.z);
            hi.w = tf32r(v.w); lo.w = tf32r(v.w - hi.w);
            *(float4*)&Ah[r0][c4] = hi; *(float4*)&Al[r0][c4] = lo;
            v = av1;
            hi.x = tf32r(v.x); lo.x = tf32r(v.x - hi.x);
            hi.y = tf32r(v.y); lo.y = tf32r(v.y - hi.y);
            hi.z = tf32r(v.z); lo.z = tf32r(v.z - hi.z);
            hi.w = tf32r(v.w); lo.w = tf32r(v.w - hi.w);
            *(float4*)&Ah[r1][c4] = hi; *(float4*)&Al[r1][c4] = lo;
            v = wv0;
            hi.x = tf32r(v.x); lo.x = tf32r(v.x - hi.x);
            hi.y = tf32r(v.y); lo.y = tf32r(v.y - hi.y);
            hi.z = tf32r(v.z); lo.z = tf32r(v.z - hi.z);
            hi.w = tf32r(v.w); lo.w = tf32r(v.w - hi.w);
            *(float4*)&Wh[r0][c4] = hi; *(float4*)&Wl[r0][c4] = lo;
            v = wv1;
            hi.x = tf32r(v.x); lo.x = tf32r(v.x - hi.x);
            hi.y = tf32r(v.y); lo.y = tf32r(v.y - hi.y);
            hi.z = tf32r(v.z); lo.z = tf32r(v.z - hi.z);
            hi.w = tf32r(v.w); lo.w = tf32r(v.w - hi.w);
            *(float4*)&Wh[r1][c4] = hi; *(float4*)&Wl[r1][c4] = lo;
        }
        __syncthreads();

        if (kt + 1 < nk) {  // prefetch next k-tile
            const int co = (kt + 1) * 16 + c4;
            av0 = *(const float4*)&Ag[(size_t)r0 * K + co];
            av1 = *(const float4*)&Ag[(size_t)r1 * K + co];
            wv0 = *(const float4*)&Wg[(size_t)r0 * K + co];
            wv1 = *(const float4*)&Wg[(size_t)r1 * K + co];
        }

        #pragma unroll
        for (int kk = 0; kk < 2; kk++) {
            const int kb = kk * 8;
            unsigned ah[4][4], al[4][4], bh[4][2], bl[4][2];
            #pragma unroll
            for (int mt = 0; mt < 4; mt++) {
                int r = m0 + mt * 16 + g;
                ah[mt][0] = __float_as_uint(Ah[r][kb + tg]);
                ah[mt][1] = __float_as_uint(Ah[r + 8][kb + tg]);
                ah[mt][2] = __float_as_uint(Ah[r][kb + tg + 4]);
                ah[mt][3] = __float_as_uint(Ah[r + 8][kb + tg + 4]);
                al[mt][0] = __float_as_uint(Al[r][kb + tg]);
                al[mt][1] = __float_as_uint(Al[r + 8][kb + tg]);
                al[mt][2] = __float_as_uint(Al[r][kb + tg + 4]);
                al[mt][3] = __float_as_uint(Al[r + 8][kb + tg + 4]);
            }
            #pragma unroll
            for (int nt = 0; nt < 4; nt++) {
                int c = n0 + nt * 8 + g;
                bh[nt][0] = __float_as_uint(Wh[c][kb + tg]);
                bh[nt][1] = __float_as_uint(Wh[c][kb + tg + 4]);
                bl[nt][0] = __float_as_uint(Wl[c][kb + tg]);
                bl[nt][1] = __float_as_uint(Wl[c][kb + tg + 4]);
            }
            #pragma unroll
            for (int mt = 0; mt < 4; mt++)
                #pragma unroll
                for (int nt = 0; nt < 4; nt++) {
                    mma_tf32(acc[mt][nt], ah[mt][0], ah[mt][1], ah[mt][2], ah[mt][3], bh[nt][0], bh[nt][1]);
                    mma_tf32(acc[mt][nt], ah[mt][0], ah[mt][1], ah[mt][2], ah[mt][3], bl[nt][0], bl[nt][1]);
                    mma_tf32(acc[mt][nt], al[mt][0], al[mt][1], al[mt][2], al[mt][3], bh[nt][0], bh[nt][1]);
                }
        }
    }

    // epilogue
    #pragma unroll
    for (int mt = 0; mt < 4; mt++) {
        int row = by * 128 + m0 + mt * 16 + g;
        #pragma unroll
        for (int nt = 0; nt < 4; nt++) {
            int col = bx * 128 + n0 + nt * 8 + tg * 2;
            float2 v0 = make_float2(acc[mt][nt][0], acc[mt][nt][1]);
            float2 v1 = make_float2(acc[mt][nt][2], acc[mt][nt][3]);
            *(float2*)&C[(size_t)row * N + col]       = v0;
            *(float2*)&C[(size_t)(row + 8) * N + col] = v1;
        }
    }
}

// ---------------------------------------------------------------------------
// Tensor-core flash attention (tf32), log2-domain online softmax.
// Block: 128 q-rows, 8 warps x 16 rows. Key tiles of 64. DK=64.
// Smem: Vs[64][72] | PK[128][68] (K tile overlays P rows 0..63).
// ---------------------------------------------------------------------------
static constexpr int VS = 72;
static constexpr int PS = 68;

__global__ __launch_bounds__(256)
void attn_tc(const float* __restrict__ Q, const float* __restrict__ K,
             const float* __restrict__ V, float* __restrict__ ctx) {
    extern __shared__ float sm[];
    float* Vs = sm;              // [64][72]
    float* PK = sm + 64 * VS;    // [128][68]; K tile = rows 0..63

    const int tid  = threadIdx.x;
    const int lane = tid & 31;
    const int w    = tid >> 5;
    const int g    = lane >> 2;
    const int tg   = lane & 3;
    const int b    = blockIdx.z;
    const int h    = blockIdx.y;
    const int qrow = blockIdx.x * 128 + w * 16;

    // Q fragments: scale*log2(e) folded in, tf32-rounded
    const float cs = 0.125f * 1.44269504088896340736f;
    unsigned qa[8][4];
    const float* Qb = Q + ((size_t)(b * S + qrow) * D + h * DK);
    #pragma unroll
    for (int ks = 0; ks < 8; ks++) {
        int c = ks * 8 + tg;
        qa[ks][0] = f2tf(Qb[(size_t)g * D + c] * cs);
        qa[ks][1] = f2tf(Qb[(size_t)(g + 8) * D + c] * cs);
        qa[ks][2] = f2tf(Qb[(size_t)g * D + c + 4] * cs);
        qa[ks][3] = f2tf(Qb[(size_t)(g + 8) * D + c + 4] * cs);
    }

    float o[8][4] = {};
    float m0v = -1e30f, m1v = -1e30f, l0 = 0.f, l1 = 0.f;

    const float* Kb = K + ((size_t)b * S * D + h * DK);
    const float* Vb = V + ((size_t)b * S * D + h * DK);
    float* Pr = PK + (size_t)(w * 16) * PS;   // this warp's P rows

    for (int kt = 0; kt < S; kt += 64) {
        __syncthreads();   // prior tile's PV reads of Vs/P done
        // cooperative K/V tile load (tf32-rounded): 64x16 float4
        for (int i = tid; i < 1024; i += 256) {
            int r = i >> 4, cc = (i & 15) << 2;
            float4 kv = *(const float4*)&Kb[(size_t)(kt + r) * D + cc];
            float4 vv = *(const float4*)&Vb[(size_t)(kt + r) * D + cc];
            kv.x = tf32r(kv.x); kv.y = tf32r(kv.y); kv.z = tf32r(kv.z); kv.w = tf32r(kv.w);
            vv.x = tf32r(vv.x); vv.y = tf32r(vv.y); vv.z = tf32r(vv.z); vv.w = tf32r(vv.w);
            *(float4*)&PK[r * PS + cc] = kv;
            *(float4*)&Vs[r * VS + cc] = vv;
        }
        __syncthreads();

        // S = Q @ K^T (log2-scaled)
        float s[8][4] = {};
        #pragma unroll
        for (int ks = 0; ks < 8; ks++) {
            const int kb = ks * 8;
            #pragma unroll
            for (int nt = 0; nt < 8; nt++) {
                unsigned b0 = __float_as_uint(PK[(nt * 8 + g) * PS + kb + tg]);
                unsigned b1 = __float_as_uint(PK[(nt * 8 + g) * PS + kb + tg + 4]);
                mma_tf32(s[nt], qa[ks][0], qa[ks][1], qa[ks][2], qa[ks][3], b0, b1);
            }
        }
        __syncthreads();   // all warps done reading K tile (P will overwrite it)

        // online softmax (rows g and g+8)
        float mx0 = -1e30f, mx1 = -1e30f;
        #pragma unroll
        for (int nt = 0; nt < 8; nt++) {
            mx0 = fmaxf(mx0, fmaxf(s[nt][0], s[nt][1]));
            mx1 = fmaxf(mx1, fmaxf(s[nt][2], s[nt][3]));
        }
        mx0 = fmaxf(mx0, __shfl_xor_sync(0xffffffffu, mx0, 1));
        mx0 = fmaxf(mx0, __shfl_xor_sync(0xffffffffu, mx0, 2));
        mx1 = fmaxf(mx1, __shfl_xor_sync(0xffffffffu, mx1, 1));
        mx1 = fmaxf(mx1, __shfl_xor_sync(0xffffffffu, mx1, 2));

        float mn0 = fmaxf(m0v, mx0), mn1 = fmaxf(m1v, mx1);
        float a0 = ex2(m0v - mn0), a1 = ex2(m1v - mn1);
        m0v = mn0; m1v = mn1;
        l0 *= a0; l1 *= a1;
        #pragma unroll
        for (int nt = 0; nt < 8; nt++) {
            o[nt][0] *= a0; o[nt][1] *= a0;
            o[nt][2] *= a1; o[nt][3] *= a1;
        }
        // p = exp2(s - m), quantize to tf32, store to P, accumulate l
        #pragma unroll
        for (int nt = 0; nt < 8; nt++) {
            float p0 = tf32r(ex2(s[nt][0] - mn0));
            float p1 = tf32r(ex2(s[nt][1] - mn0));
            float p2 = tf32r(ex2(s[nt][2] - mn1));
            float p3 = tf32r(ex2(s[nt][3] - mn1));
            l0 += p0 + p1; l1 += p2 + p3;
            int c = nt * 8 + tg * 2;
            *(float2*)&Pr[(size_t)g * PS + c]       = make_float2(p0, p1);
            *(float2*)&Pr[(size_t)(g + 8) * PS + c] = make_float2(p2, p3);
        }
        __syncwarp();

        // O += P @ V
        #pragma unroll
        for (int ks = 0; ks < 8; ks++) {
            const int kb = ks * 8;
            unsigned pa0 = __float_as_uint(Pr[(size_t)g * PS + kb + tg]);
            unsigned pa1 = __float_as_uint(Pr[(size_t)(g + 8) * PS + kb + tg]);
            unsigned pa2 = __float_as_uint(Pr[(size_t)g * PS + kb + tg + 4]);
            unsigned pa3 = __float_as_uint(Pr[(size_t)(g + 8) * PS + kb + tg + 4]);
            #pragma unroll
            for (int nt = 0; nt < 8; nt++) {
                unsigned b0 = __float_as_uint(Vs[(kb + tg) * VS + nt * 8 + g]);
                unsigned b1 = __float_as_uint(Vs[(kb + tg + 4) * VS + nt * 8 + g]);
                mma_tf32(o[nt], pa0, pa1, pa2, pa3, b0, b1);
            }
        }
    }

    // finalize: row sums of l across the 4 lanes of each group
    l0 += __shfl_xor_sync(0xffffffffu, l0, 1);
    l0 += __shfl_xor_sync(0xffffffffu, l0, 2);
    l1 += __shfl_xor_sync(0xffffffffu, l1, 1);
    l1 += __shfl_xor_sync(0xffffffffu, l1, 2);
    const float i0 = 1.f / l0, i1 = 1.f / l1;

    float* Ob = ctx + ((size_t)(b * S + qrow) * D + h * DK);
    #pragma unroll
    for (int nt = 0; nt < 8; nt++) {
        int c = nt * 8 + tg * 2;
        *(float2*)&Ob[(size_t)g * D + c]       = make_float2(o[nt][0] * i0, o[nt][1] * i0);
        *(float2*)&Ob[(size_t)(g + 8) * D + c] = make_float2(o[nt][2] * i1, o[nt][3] * i1);
    }
}

// ---------------------------------------------------------------------------
// Launch
// ---------------------------------------------------------------------------
extern "C" void kernel_launch(void* const* d_in, const int* in_sizes, int n_in,
                              void* d_out, int out_size) {
    const float* query = (const float*)d_in[0];
    const float* key   = (const float*)d_in[1];
    const float* value = (const float*)d_in[2];
    const float* w_q   = (const float*)d_in[3];
    const float* w_k   = (const float*)d_in[4];
    const float* w_v   = (const float*)d_in[5];
    const float* w_o   = (const float*)d_in[6];
    float* out = (float*)d_out;

    float *Qp, *Kp, *Vp, *Cp;
    cudaGetSymbolAddress((void**)&Qp, g_Q);
    cudaGetSymbolAddress((void**)&Kp, g_K);
    cudaGetSymbolAddress((void**)&Vp, g_V);
    cudaGetSymbolAddress((void**)&Cp, g_C);

    const int M = B * S;                  // 4096
    dim3 ggrid(D / 128, M / 128);         // (8, 32)

    gemm_tf32x3<<<ggrid, 256>>>(query, w_q, Qp, M, D, D);
    gemm_tf32x3<<<ggrid, 256>>>(key,   w_k, Kp, M, D, D);
    gemm_tf32x3<<<ggrid, 256>>>(value, w_v, Vp, M, D, D);

    const int smem_attn = (64 * VS + 128 * PS) * (int)sizeof(float);  // 53248
    cudaFuncSetAttribute(attn_tc, cudaFuncAttributeMaxDynamicSharedMemorySize, smem_attn);
    dim3 agrid(S / 128, H, B);            // (16, 16, 2)
    attn_tc<<<agrid, 256, smem_attn>>>(Qp, Kp, Vp, Cp);

    gemm_tf32x3<<<ggrid, 256>>>(Cp, w_o, out, M, D, D);
}

// round 3
// speedup vs baseline: 3.3682x; 1.3927x over previous
#include <cuda_runtime.h>
#include <cuda_bf16.h>
#include <cstdint>

static constexpr int B  = 2;
static constexpr int S  = 2048;
static constexpr int D  = 1024;
static constexpr int H  = 16;
static constexpr int DK = 64;

// Scratch (device globals: allocation-free rule)
__device__ float g_Q[B * S * D];
__device__ float g_K[B * S * D];
__device__ float g_V[B * S * D];
__device__ float g_C[B * S * D];
__device__ __nv_bfloat16 g_Ah[B * S * D];   // activation hi split
__device__ __nv_bfloat16 g_Al[B * S * D];   // activation lo split
__device__ __nv_bfloat16 g_Wh[D * D];       // weight hi split
__device__ __nv_bfloat16 g_Wl[D * D];       // weight lo split

// ---------------------------------------------------------------------------
// helpers
// ---------------------------------------------------------------------------
__device__ __forceinline__ unsigned f2tf(float x) {
    unsigned u;
    asm("cvt.rna.tf32.f32 %0, %1;" : "=r"(u) : "f"(x));
    return u;
}
__device__ __forceinline__ float tf32r(float x) { return __uint_as_float(f2tf(x)); }

__device__ __forceinline__ float ex2(float x) {
    float r;
    asm("ex2.approx.f32 %0, %1;" : "=f"(r) : "f"(x));
    return r;
}

__device__ __forceinline__ void mma_tf32(float c[4],
                                         unsigned a0, unsigned a1, unsigned a2, unsigned a3,
                                         unsigned b0, unsigned b1) {
    asm("mma.sync.aligned.m16n8k8.row.col.f32.tf32.tf32.f32 "
        "{%0,%1,%2,%3}, {%4,%5,%6,%7}, {%8,%9}, {%0,%1,%2,%3};"
        : "+f"(c[0]), "+f"(c[1]), "+f"(c[2]), "+f"(c[3])
        : "r"(a0), "r"(a1), "r"(a2), "r"(a3), "r"(b0), "r"(b1));
}

__device__ __forceinline__ void mma_bf16(float c[4], const unsigned a[4],
                                         unsigned b0, unsigned b1) {
    asm("mma.sync.aligned.m16n8k16.row.col.f32.bf16.bf16.f32 "
        "{%0,%1,%2,%3}, {%4,%5,%6,%7}, {%8,%9}, {%0,%1,%2,%3};"
        : "+f"(c[0]), "+f"(c[1]), "+f"(c[2]), "+f"(c[3])
        : "r"(a[0]), "r"(a[1]), "r"(a[2]), "r"(a[3]), "r"(b0), "r"(b1));
}

__device__ __forceinline__ void ldm4(unsigned r[4], const __nv_bfloat16* p) {
    unsigned s = (unsigned)__cvta_generic_to_shared(p);
    asm volatile("ldmatrix.sync.aligned.m8n8.x4.shared.b16 {%0,%1,%2,%3}, [%4];"
                 : "=r"(r[0]), "=r"(r[1]), "=r"(r[2]), "=r"(r[3]) : "r"(s));
}

__device__ __forceinline__ void cp16(const __nv_bfloat16* smem, const __nv_bfloat16* gmem) {
    unsigned s = (unsigned)__cvta_generic_to_shared(smem);
    asm volatile("cp.async.ca.shared.global [%0], [%1], 16;" :: "r"(s), "l"(gmem));
}
#define CP_COMMIT() asm volatile("cp.async.commit_group;")
#define CP_WAIT1()  asm volatile("cp.async.wait_group 1;")
#define CP_WAIT0()  asm volatile("cp.async.wait_group 0;")

// ---------------------------------------------------------------------------
// fp32 -> bf16 hi/lo split prepass (vectorized, 4 elems/thread)
// ---------------------------------------------------------------------------
__global__ __launch_bounds__(256)
void split_bf16(const float* __restrict__ in, __nv_bfloat16* __restrict__ hi,
                __nv_bfloat16* __restrict__ lo, int n4) {
    int i = blockIdx.x * blockDim.x + threadIdx.x;
    if (i >= n4) return;
    float4 v = ((const float4*)in)[i];
    __nv_bfloat16 h0 = __float2bfloat16_rn(v.x);
    __nv_bfloat16 h1 = __float2bfloat16_rn(v.y);
    __nv_bfloat16 h2 = __float2bfloat16_rn(v.z);
    __nv_bfloat16 h3 = __float2bfloat16_rn(v.w);
    __nv_bfloat16 l0 = __float2bfloat16_rn(v.x - __bfloat162float(h0));
    __nv_bfloat16 l1 = __float2bfloat16_rn(v.y - __bfloat162float(h1));
    __nv_bfloat16 l2 = __float2bfloat16_rn(v.z - __bfloat162float(h2));
    __nv_bfloat16 l3 = __float2bfloat16_rn(v.w - __bfloat162float(h3));
    __nv_bfloat162 hv0 = {h0, h1}, hv1 = {h2, h3};
    __nv_bfloat162 lv0 = {l0, l1}, lv1 = {l2, l3};
    ((uint2*)hi)[i] = make_uint2(*(unsigned*)&hv0, *(unsigned*)&hv1);
    ((uint2*)lo)[i] = make_uint2(*(unsigned*)&lv0, *(unsigned*)&lv1);
}

// ---------------------------------------------------------------------------
// bf16x3 GEMM: C[M,N] = A[M,K] @ W[N,K]^T with fp32-like accuracy (~3e-5).
// A ~= Ah + Al, W ~= Wh + Wl; C = Ah*Wh + Ah*Wl + Al*Wh (fp32 accum).
// BM=BN=128, BK=32, 256 threads, warp tile 64x32, cp.async double-buffer,
// ldmatrix fragment loads (40-elem row stride -> conflict-free LDSM).
// ---------------------------------------------------------------------------
static constexpr int LDR = 40;          // smem row stride (bf16 elems)
static constexpr int ASZ = 128 * LDR;   // elems per operand array per stage

__global__ __launch_bounds__(256, 2)
void gemm_bf16x3(const __nv_bfloat16* __restrict__ Ah, const __nv_bfloat16* __restrict__ Al,
                 const __nv_bfloat16* __restrict__ Wh, const __nv_bfloat16* __restrict__ Wl,
                 float* __restrict__ C, int M, int N, int K) {
    extern __shared__ __nv_bfloat16 sm[];   // 2 stages x {Ah,Al,Wh,Wl}[128][40]

    const int tid  = threadIdx.x;
    const int lane = tid & 31;
    const int warp = tid >> 5;
    const int g    = lane >> 2;
    const int tg   = lane & 3;
    const int m0   = (warp >> 2) * 64;
    const int n0   = (warp & 3) * 32;
    const int bx   = blockIdx.x, by = blockIdx.y;

    const __nv_bfloat16* gAh = Ah + (size_t)(by * 128) * K;
    const __nv_bfloat16* gAl = Al + (size_t)(by * 128) * K;
    const __nv_bfloat16* gWh = Wh + (size_t)(bx * 128) * K;
    const __nv_bfloat16* gWl = Wl + (size_t)(bx * 128) * K;

    // loader mapping: 512 16B-segments per array per stage; this thread does
    // segs tid and tid+256. seg s: row=s>>2, col8=(s&3)*8.
    const int r0 = tid >> 2,        c0 = (tid & 3) * 8;
    const int r1 = (tid + 256) >> 2, c1 = ((tid + 256) & 3) * 8;

    float acc[4][4][4] = {};

    auto issue = [&](int kt, int st) {
        __nv_bfloat16* base = sm + (size_t)st * 4 * ASZ;
        const int ko = kt * 32;
        cp16(base + 0 * ASZ + r0 * LDR + c0, gAh + (size_t)r0 * K + ko + c0);
        cp16(base + 0 * ASZ + r1 * LDR + c1, gAh + (size_t)r1 * K + ko + c1);
        cp16(base + 1 * ASZ + r0 * LDR + c0, gAl + (size_t)r0 * K + ko + c0);
        cp16(base + 1 * ASZ + r1 * LDR + c1, gAl + (size_t)r1 * K + ko + c1);
        cp16(base + 2 * ASZ + r0 * LDR + c0, gWh + (size_t)r0 * K + ko + c0);
        cp16(base + 2 * ASZ + r1 * LDR + c1, gWh + (size_t)r1 * K + ko + c1);
        cp16(base + 3 * ASZ + r0 * LDR + c0, gWl + (size_t)r0 * K + ko + c0);
        cp16(base + 3 * ASZ + r1 * LDR + c1, gWl + (size_t)r1 * K + ko + c1);
    };

    const int lr = lane & 15;           // ldmatrix row within 16-row tile
    const int lc = (lane >> 4) * 8;     // ldmatrix col half

    issue(0, 0); CP_COMMIT();

    const int nk = K / 32;
    for (int kt = 0; kt < nk; kt++) {
        if (kt + 1 < nk) { issue(kt + 1, (kt + 1) & 1); CP_COMMIT(); CP_WAIT1(); }
        else             { CP_WAIT0(); }
        __syncthreads();

        const __nv_bfloat16* bAh = sm + (size_t)(kt & 1) * 4 * ASZ;
        const __nv_bfloat16* bAl = bAh + ASZ;
        const __nv_bfloat16* bWh = bAl + ASZ;
        const __nv_bfloat16* bWl = bWh + ASZ;

        #pragma unroll
        for (int kk = 0; kk < 2; kk++) {
            const int co = kk * 16 + lc;
            // B fragments: bh[2*nt], bh[2*nt+1] for n-tiles 0..3
            unsigned bh[8], bl[8], t[4];
            ldm4(t, bWh + (n0 +      lr) * LDR + co);
            bh[0] = t[0]; bh[1] = t[2]; bh[2] = t[1]; bh[3] = t[3];
            ldm4(t, bWh + (n0 + 16 + lr) * LDR + co);
            bh[4] = t[0]; bh[5] = t[2]; bh[6] = t[1]; bh[7] = t[3];
            ldm4(t, bWl + (n0 +      lr) * LDR + co);
            bl[0] = t[0]; bl[1] = t[2]; bl[2] = t[1]; bl[3] = t[3];
            ldm4(t, bWl + (n0 + 16 + lr) * LDR + co);
            bl[4] = t[0]; bl[5] = t[2]; bl[6] = t[1]; bl[7] = t[3];

            #pragma unroll
            for (int mt = 0; mt < 4; mt++) {
                unsigned ah[4], al[4];
                ldm4(ah, bAh + (m0 + mt * 16 + lr) * LDR + co);
                ldm4(al, bAl + (m0 + mt * 16 + lr) * LDR + co);
                #pragma unroll
                for (int nt = 0; nt < 4; nt++) {
                    mma_bf16(acc[mt][nt], ah, bh[2 * nt], bh[2 * nt + 1]);
                    mma_bf16(acc[mt][nt], ah, bl[2 * nt], bl[2 * nt + 1]);
                    mma_bf16(acc[mt][nt], al, bh[2 * nt], bh[2 * nt + 1]);
                }
            }
        }
        __syncthreads();
    }

    #pragma unroll
    for (int mt = 0; mt < 4; mt++) {
        int row = by * 128 + m0 + mt * 16 + g;
        #pragma unroll
        for (int nt = 0; nt < 4; nt++) {
            int col = bx * 128 + n0 + nt * 8 + tg * 2;
            *(float2*)&C[(size_t)row * N + col]       = make_float2(acc[mt][nt][0], acc[mt][nt][1]);
            *(float2*)&C[(size_t)(row + 8) * N + col] = make_float2(acc[mt][nt][2], acc[mt][nt][3]);
        }
    }
}

// ---------------------------------------------------------------------------
// Tensor-core flash attention (tf32), log2-domain online softmax. (unchanged)
// ---------------------------------------------------------------------------
static constexpr int VS = 72;
static constexpr int PS = 68;

__global__ __launch_bounds__(256)
void attn_tc(const float* __restrict__ Q, const float* __restrict__ K,
             const float* __restrict__ V, float* __restrict__ ctx) {
    extern __shared__ float smf[];
    float* Vs = smf;             // [64][72]
    float* PK = smf + 64 * VS;   // [128][68]; K tile = rows 0..63

    const int tid  = threadIdx.x;
    const int lane = tid & 31;
    const int w    = tid >> 5;
    const int g    = lane >> 2;
    const int tg   = lane & 3;
    const int b    = blockIdx.z;
    const int h    = blockIdx.y;
    const int qrow = blockIdx.x * 128 + w * 16;

    const float cs = 0.125f * 1.44269504088896340736f;
    unsigned qa[8][4];
    const float* Qb = Q + ((size_t)(b * S + qrow) * D + h * DK);
    #pragma unroll
    for (int ks = 0; ks < 8; ks++) {
        int c = ks * 8 + tg;
        qa[ks][0] = f2tf(Qb[(size_t)g * D + c] * cs);
        qa[ks][1] = f2tf(Qb[(size_t)(g + 8) * D + c] * cs);
        qa[ks][2] = f2tf(Qb[(size_t)g * D + c + 4] * cs);
        qa[ks][3] = f2tf(Qb[(size_t)(g + 8) * D + c + 4] * cs);
    }

    float o[8][4] = {};
    float m0v = -1e30f, m1v = -1e30f, l0 = 0.f, l1 = 0.f;

    const float* Kb = K + ((size_t)b * S * D + h * DK);
    const float* Vb = V + ((size_t)b * S * D + h * DK);
    float* Pr = PK + (size_t)(w * 16) * PS;

    for (int kt = 0; kt < S; kt += 64) {
        __syncthreads();
        for (int i = tid; i < 1024; i += 256) {
            int r = i >> 4, cc = (i & 15) << 2;
            float4 kv = *(const float4*)&Kb[(size_t)(kt + r) * D + cc];
            float4 vv = *(const float4*)&Vb[(size_t)(kt + r) * D + cc];
            kv.x = tf32r(kv.x); kv.y = tf32r(kv.y); kv.z = tf32r(kv.z); kv.w = tf32r(kv.w);
            vv.x = tf32r(vv.x); vv.y = tf32r(vv.y); vv.z = tf32r(vv.z); vv.w = tf32r(vv.w);
            *(float4*)&PK[r * PS + cc] = kv;
            *(float4*)&Vs[r * VS + cc] = vv;
        }
        __syncthreads();

        float s[8][4] = {};
        #pragma unroll
        for (int ks = 0; ks < 8; ks++) {
            const int kb = ks * 8;
            #pragma unroll
            for (int nt = 0; nt < 8; nt++) {
                unsigned b0 = __float_as_uint(PK[(nt * 8 + g) * PS + kb + tg]);
                unsigned b1 = __float_as_uint(PK[(nt * 8 + g) * PS + kb + tg + 4]);
                mma_tf32(s[nt], qa[ks][0], qa[ks][1], qa[ks][2], qa[ks][3], b0, b1);
            }
        }
        __syncthreads();

        float mx0 = -1e30f, mx1 = -1e30f;
        #pragma unroll
        for (int nt = 0; nt < 8; nt++) {
            mx0 = fmaxf(mx0, fmaxf(s[nt][0], s[nt][1]));
            mx1 = fmaxf(mx1, fmaxf(s[nt][2], s[nt][3]));
        }
        mx0 = fmaxf(mx0, __shfl_xor_sync(0xffffffffu, mx0, 1));
        mx0 = fmaxf(mx0, __shfl_xor_sync(0xffffffffu, mx0, 2));
        mx1 = fmaxf(mx1, __shfl_xor_sync(0xffffffffu, mx1, 1));
        mx1 = fmaxf(mx1, __shfl_xor_sync(0xffffffffu, mx1, 2));

        float mn0 = fmaxf(m0v, mx0), mn1 = fmaxf(m1v, mx1);
        float a0 = ex2(m0v - mn0), a1 = ex2(m1v - mn1);
        m0v = mn0; m1v = mn1;
        l0 *= a0; l1 *= a1;
        #pragma unroll
        for (int nt = 0; nt < 8; nt++) {
            o[nt][0] *= a0; o[nt][1] *= a0;
            o[nt][2] *= a1; o[nt][3] *= a1;
        }
        #pragma unroll
        for (int nt = 0; nt < 8; nt++) {
            float p0 = tf32r(ex2(s[nt][0] - mn0));
            float p1 = tf32r(ex2(s[nt][1] - mn0));
            float p2 = tf32r(ex2(s[nt][2] - mn1));
            float p3 = tf32r(ex2(s[nt][3] - mn1));
            l0 += p0 + p1; l1 += p2 + p3;
            int c = nt * 8 + tg * 2;
            *(float2*)&Pr[(size_t)g * PS + c]       = make_float2(p0, p1);
            *(float2*)&Pr[(size_t)(g + 8) * PS + c] = make_float2(p2, p3);
        }
        __syncwarp();

        #pragma unroll
        for (int ks = 0; ks < 8; ks++) {
            const int kb = ks * 8;
            unsigned pa0 = __float_as_uint(Pr[(size_t)g * PS + kb + tg]);
            unsigned pa1 = __float_as_uint(Pr[(size_t)(g + 8) * PS + kb + tg]);
            unsigned pa2 = __float_as_uint(Pr[(size_t)g * PS + kb + tg + 4]);
            unsigned pa3 = __float_as_uint(Pr[(size_t)(g + 8) * PS + kb + tg + 4]);
            #pragma unroll
            for (int nt = 0; nt < 8; nt++) {
                unsigned b0 = __float_as_uint(Vs[(kb + tg) * VS + nt * 8 + g]);
                unsigned b1 = __float_as_uint(Vs[(kb + tg + 4) * VS + nt * 8 + g]);
                mma_tf32(o[nt], pa0, pa1, pa2, pa3, b0, b1);
            }
        }
    }

    l0 += __shfl_xor_sync(0xffffffffu, l0, 1);
    l0 += __shfl_xor_sync(0xffffffffu, l0, 2);
    l1 += __shfl_xor_sync(0xffffffffu, l1, 1);
    l1 += __shfl_xor_sync(0xffffffffu, l1, 2);
    const float i0 = 1.f / l0, i1 = 1.f / l1;

    float* Ob = ctx + ((size_t)(b * S + qrow) * D + h * DK);
    #pragma unroll
    for (int nt = 0; nt < 8; nt++) {
        int c = nt * 8 + tg * 2;
        *(float2*)&Ob[(size_t)g * D + c]       = make_float2(o[nt][0] * i0, o[nt][1] * i0);
        *(float2*)&Ob[(size_t)(g + 8) * D + c] = make_float2(o[nt][2] * i1, o[nt][3] * i1);
    }
}

// ---------------------------------------------------------------------------
// Launch
// ---------------------------------------------------------------------------
extern "C" void kernel_launch(void* const* d_in, const int* in_sizes, int n_in,
                              void* d_out, int out_size) {
    const float* query = (const float*)d_in[0];
    const float* key   = (const float*)d_in[1];
    const float* value = (const float*)d_in[2];
    const float* w_q   = (const float*)d_in[3];
    const float* w_k   = (const float*)d_in[4];
    const float* w_v   = (const float*)d_in[5];
    const float* w_o   = (const float*)d_in[6];
    float* out = (float*)d_out;

    float *Qp, *Kp, *Vp, *Cp;
    __nv_bfloat16 *Ahp, *Alp, *Whp, *Wlp;
    cudaGetSymbolAddress((void**)&Qp,  g_Q);
    cudaGetSymbolAddress((void**)&Kp,  g_K);
    cudaGetSymbolAddress((void**)&Vp,  g_V);
    cudaGetSymbolAddress((void**)&Cp,  g_C);
    cudaGetSymbolAddress((void**)&Ahp, g_Ah);
    cudaGetSymbolAddress((void**)&Alp, g_Al);
    cudaGetSymbolAddress((void**)&Whp, g_Wh);
    cudaGetSymbolAddress((void**)&Wlp, g_Wl);

    const int M = B * S;                  // 4096
    dim3 ggrid(D / 128, M / 128);         // (8, 32)
    const int act4 = M * D / 4;           // 1M
    const int wgt4 = D * D / 4;           // 256K

    const int smem_gemm = 2 * 4 * ASZ * (int)sizeof(__nv_bfloat16);  // 81920
    cudaFuncSetAttribute(gemm_bf16x3, cudaFuncAttributeMaxDynamicSharedMemorySize, smem_gemm);

    // Q projection
    split_bf16<<<(wgt4 + 255) / 256, 256>>>(w_q,   Whp, Wlp, wgt4);
    split_bf16<<<(act4 + 255) / 256, 256>>>(query, Ahp, Alp, act4);
    gemm_bf16x3<<<ggrid, 256, smem_gemm>>>(Ahp, Alp, Whp, Wlp, Qp, M, D, D);
    // K projection
    split_bf16<<<(wgt4 + 255) / 256, 256>>>(w_k, Whp, Wlp, wgt4);
    split_bf16<<<(act4 + 255) / 256, 256>>>(key, Ahp, Alp, act4);
    gemm_bf16x3<<<ggrid, 256, smem_gemm>>>(Ahp, Alp, Whp, Wlp, Kp, M, D, D);
    // V projection
    split_bf16<<<(wgt4 + 255) / 256, 256>>>(w_v,   Whp, Wlp, wgt4);
    split_bf16<<<(act4 + 255) / 256, 256>>>(value, Ahp, Alp, act4);
    gemm_bf16x3<<<ggrid, 256, smem_gemm>>>(Ahp, Alp, Whp, Wlp, Vp, M, D, D);

    // attention
    const int smem_attn = (64 * VS + 128 * PS) * (int)sizeof(float);  // 53248
    cudaFuncSetAttribute(attn_tc, cudaFuncAttributeMaxDynamicSharedMemorySize, smem_attn);
    dim3 agrid(S / 128, H, B);            // (16, 16, 2)
    attn_tc<<<agrid, 256, smem_attn>>>(Qp, Kp, Vp, Cp);

    // output projection
    split_bf16<<<(wgt4 + 255) / 256, 256>>>(w_o, Whp, Wlp, wgt4);
    split_bf16<<<(act4 + 255) / 256, 256>>>(Cp,  Ahp, Alp, act4);
    gemm_bf16x3<<<ggrid, 256, smem_gemm>>>(Ahp, Alp, Whp, Wlp, out, M, D, D);
}

// round 5
// speedup vs baseline: 3.6175x; 1.0740x over previous
#include <cuda_runtime.h>
#include <cuda_bf16.h>
#include <cstdint>

static constexpr int B  = 2;
static constexpr int S  = 2048;
static constexpr int D  = 1024;
static constexpr int H  = 16;
static constexpr int DK = 64;

// Scratch (device globals: allocation-free rule)
__device__ float g_Q[B * S * D];
__device__ float g_K[B * S * D];
__device__ float g_V[B * S * D];
__device__ float g_C[B * S * D];
__device__ __nv_bfloat16 g_Ah[B * S * D];   // activation hi split
__device__ __nv_bfloat16 g_Al[B * S * D];   // activation lo split
__device__ __nv_bfloat16 g_Wh[D * D];       // weight hi split
__device__ __nv_bfloat16 g_Wl[D * D];       // weight lo split

// ---------------------------------------------------------------------------
// helpers
// ---------------------------------------------------------------------------
__device__ __forceinline__ unsigned f2tf(float x) {
    unsigned u;
    asm("cvt.rna.tf32.f32 %0, %1;" : "=r"(u) : "f"(x));
    return u;
}
__device__ __forceinline__ float tf32r(float x) { return __uint_as_float(f2tf(x)); }

__device__ __forceinline__ float ex2(float x) {
    float r;
    asm("ex2.approx.f32 %0, %1;" : "=f"(r) : "f"(x));
    return r;
}

__device__ __forceinline__ void mma_tf32(float c[4],
                                         unsigned a0, unsigned a1, unsigned a2, unsigned a3,
                                         unsigned b0, unsigned b1) {
    asm("mma.sync.aligned.m16n8k8.row.col.f32.tf32.tf32.f32 "
        "{%0,%1,%2,%3}, {%4,%5,%6,%7}, {%8,%9}, {%0,%1,%2,%3};"
        : "+f"(c[0]), "+f"(c[1]), "+f"(c[2]), "+f"(c[3])
        : "r"(a0), "r"(a1), "r"(a2), "r"(a3), "r"(b0), "r"(b1));
}

__device__ __forceinline__ void mma_bf16(float c[4], const unsigned a[4],
                                         unsigned b0, unsigned b1) {
    asm("mma.sync.aligned.m16n8k16.row.col.f32.bf16.bf16.f32 "
        "{%0,%1,%2,%3}, {%4,%5,%6,%7}, {%8,%9}, {%0,%1,%2,%3};"
        : "+f"(c[0]), "+f"(c[1]), "+f"(c[2]), "+f"(c[3])
        : "r"(a[0]), "r"(a[1]), "r"(a[2]), "r"(a[3]), "r"(b0), "r"(b1));
}

__device__ __forceinline__ void ldm4(unsigned r[4], const __nv_bfloat16* p) {
    unsigned s = (unsigned)__cvta_generic_to_shared(p);
    asm volatile("ldmatrix.sync.aligned.m8n8.x4.shared.b16 {%0,%1,%2,%3}, [%4];"
                 : "=r"(r[0]), "=r"(r[1]), "=r"(r[2]), "=r"(r[3]) : "r"(s));
}

__device__ __forceinline__ void cp16(void* sdst, const void* gsrc) {
    unsigned s = (unsigned)__cvta_generic_to_shared(sdst);
    asm volatile("cp.async.ca.shared.global [%0], [%1], 16;" :: "r"(s), "l"(gsrc));
}
#define CP_COMMIT() asm volatile("cp.async.commit_group;")
#define CP_WAIT1()  asm volatile("cp.async.wait_group 1;")
#define CP_WAIT0()  asm volatile("cp.async.wait_group 0;")

// ---------------------------------------------------------------------------
// fp32 -> bf16 hi/lo split prepass
// ---------------------------------------------------------------------------
__global__ __launch_bounds__(256)
void split_bf16(const float* __restrict__ in, __nv_bfloat16* __restrict__ hi,
                __nv_bfloat16* __restrict__ lo, int n4) {
    int i = blockIdx.x * blockDim.x + threadIdx.x;
    if (i >= n4) return;
    float4 v = ((const float4*)in)[i];
    __nv_bfloat16 h0 = __float2bfloat16_rn(v.x);
    __nv_bfloat16 h1 = __float2bfloat16_rn(v.y);
    __nv_bfloat16 h2 = __float2bfloat16_rn(v.z);
    __nv_bfloat16 h3 = __float2bfloat16_rn(v.w);
    __nv_bfloat16 l0 = __float2bfloat16_rn(v.x - __bfloat162float(h0));
    __nv_bfloat16 l1 = __float2bfloat16_rn(v.y - __bfloat162float(h1));
    __nv_bfloat16 l2 = __float2bfloat16_rn(v.z - __bfloat162float(h2));
    __nv_bfloat16 l3 = __float2bfloat16_rn(v.w - __bfloat162float(h3));
    __nv_bfloat162 hv0 = {h0, h1}, hv1 = {h2, h3};
    __nv_bfloat162 lv0 = {l0, l1}, lv1 = {l2, l3};
    ((uint2*)hi)[i] = make_uint2(*(unsigned*)&hv0, *(unsigned*)&hv1);
    ((uint2*)lo)[i] = make_uint2(*(unsigned*)&lv0, *(unsigned*)&lv1);
}

// ---------------------------------------------------------------------------
// bf16x3 GEMM: C[M,N] = A[M,K] @ W[N,K]^T with fp32-like accuracy.
// BM=BN=128, BK=32, 256 threads, warp tile 64x32, cp.async double-buffer,
// ldmatrix. rnd!=0 -> round outputs to tf32 (for Q/K/V feeding attention).
// ---------------------------------------------------------------------------
static constexpr int LDR = 40;          // smem row stride (bf16 elems)
static constexpr int ASZ = 128 * LDR;   // elems per operand array per stage

__global__ __launch_bounds__(256, 2)
void gemm_bf16x3(const __nv_bfloat16* __restrict__ Ah, const __nv_bfloat16* __restrict__ Al,
                 const __nv_bfloat16* __restrict__ Wh, const __nv_bfloat16* __restrict__ Wl,
                 float* __restrict__ C, int M, int N, int K, int rnd) {
    extern __shared__ __nv_bfloat16 sm[];

    const int tid  = threadIdx.x;
    const int lane = tid & 31;
    const int warp = tid >> 5;
    const int g    = lane >> 2;
    const int tg   = lane & 3;
    const int m0   = (warp >> 2) * 64;
    const int n0   = (warp & 3) * 32;
    const int bx   = blockIdx.x, by = blockIdx.y;

    const __nv_bfloat16* gAh = Ah + (size_t)(by * 128) * K;
    const __nv_bfloat16* gAl = Al + (size_t)(by * 128) * K;
    const __nv_bfloat16* gWh = Wh + (size_t)(bx * 128) * K;
    const __nv_bfloat16* gWl = Wl + (size_t)(bx * 128) * K;

    const int r0 = tid >> 2,         c0 = (tid & 3) * 8;
    const int r1 = (tid + 256) >> 2, c1 = ((tid + 256) & 3) * 8;

    float acc[4][4][4] = {};

    auto issue = [&](int kt, int st) {
        __nv_bfloat16* base = sm + (size_t)st * 4 * ASZ;
        const int ko = kt * 32;
        cp16(base + 0 * ASZ + r0 * LDR + c0, gAh + (size_t)r0 * K + ko + c0);
        cp16(base + 0 * ASZ + r1 * LDR + c1, gAh + (size_t)r1 * K + ko + c1);
        cp16(base + 1 * ASZ + r0 * LDR + c0, gAl + (size_t)r0 * K + ko + c0);
        cp16(base + 1 * ASZ + r1 * LDR + c1, gAl + (size_t)r1 * K + ko + c1);
        cp16(base + 2 * ASZ + r0 * LDR + c0, gWh + (size_t)r0 * K + ko + c0);
        cp16(base + 2 * ASZ + r1 * LDR + c1, gWh + (size_t)r1 * K + ko + c1);
        cp16(base + 3 * ASZ + r0 * LDR + c0, gWl + (size_t)r0 * K + ko + c0);
        cp16(base + 3 * ASZ + r1 * LDR + c1, gWl + (size_t)r1 * K + ko + c1);
    };

    const int lr = lane & 15;
    const int lc = (lane >> 4) * 8;

    issue(0, 0); CP_COMMIT();

    const int nk = K / 32;
    for (int kt = 0; kt < nk; kt++) {
        if (kt + 1 < nk) { issue(kt + 1, (kt + 1) & 1); CP_COMMIT(); CP_WAIT1(); }
        else             { CP_WAIT0(); }
        __syncthreads();

        const __nv_bfloat16* bAh = sm + (size_t)(kt & 1) * 4 * ASZ;
        const __nv_bfloat16* bAl = bAh + ASZ;
        const __nv_bfloat16* bWh = bAl + ASZ;
        const __nv_bfloat16* bWl = bWh + ASZ;

        #pragma unroll
        for (int kk = 0; kk < 2; kk++) {
            const int co = kk * 16 + lc;
            unsigned bh[8], bl[8], t[4];
            ldm4(t, bWh + (n0 +      lr) * LDR + co);
            bh[0] = t[0]; bh[1] = t[2]; bh[2] = t[1]; bh[3] = t[3];
            ldm4(t, bWh + (n0 + 16 + lr) * LDR + co);
            bh[4] = t[0]; bh[5] = t[2]; bh[6] = t[1]; bh[7] = t[3];
            ldm4(t, bWl + (n0 +      lr) * LDR + co);
            bl[0] = t[0]; bl[1] = t[2]; bl[2] = t[1]; bl[3] = t[3];
            ldm4(t, bWl + (n0 + 16 + lr) * LDR + co);
            bl[4] = t[0]; bl[5] = t[2]; bl[6] = t[1]; bl[7] = t[3];

            #pragma unroll
            for (int mt = 0; mt < 4; mt++) {
                unsigned ah[4], al[4];
                ldm4(ah, bAh + (m0 + mt * 16 + lr) * LDR + co);
                ldm4(al, bAl + (m0 + mt * 16 + lr) * LDR + co);
                #pragma unroll
                for (int nt = 0; nt < 4; nt++) {
                    mma_bf16(acc[mt][nt], ah, bh[2 * nt], bh[2 * nt + 1]);
                    mma_bf16(acc[mt][nt], ah, bl[2 * nt], bl[2 * nt + 1]);
                    mma_bf16(acc[mt][nt], al, bh[2 * nt], bh[2 * nt + 1]);
                }
            }
        }
        __syncthreads();
    }

    #pragma unroll
    for (int mt = 0; mt < 4; mt++) {
        int row = by * 128 + m0 + mt * 16 + g;
        #pragma unroll
        for (int nt = 0; nt < 4; nt++) {
            int col = bx * 128 + n0 + nt * 8 + tg * 2;
            float v0 = acc[mt][nt][0], v1 = acc[mt][nt][1];
            float v2 = acc[mt][nt][2], v3 = acc[mt][nt][3];
            if (rnd) { v0 = tf32r(v0); v1 = tf32r(v1); v2 = tf32r(v2); v3 = tf32r(v3); }
            *(float2*)&C[(size_t)row * N + col]       = make_float2(v0, v1);
            *(float2*)&C[(size_t)(row + 8) * N + col] = make_float2(v2, v3);
        }
    }
}

// ---------------------------------------------------------------------------
// Tensor-core flash attention (tf32), cp.async double-buffered K/V tiles.
// Inputs Q/K/V are pre-rounded to tf32 by the projection epilogue.
// Block: 128 q-rows, 8 warps x 16 rows. Key tiles of 64. DK=64.
// Smem: Kst[2][64][68] | Vst[2][64][72] | P[128][68]  = 104 KB.
// ---------------------------------------------------------------------------
static constexpr int KS2 = 68;            // K tile row stride (floats)
static constexpr int VS2 = 72;            // V tile row stride
static constexpr int PS2 = 68;            // P row stride
static constexpr int KSTG = 64 * KS2;     // floats per K stage
static constexpr int VSTG = 64 * VS2;
static constexpr int A_SMEM = (2 * KSTG + 2 * VSTG + 128 * PS2) * 4;  // 106496 B

__global__ __launch_bounds__(256, 2)
void attn_tc(const float* __restrict__ Q, const float* __restrict__ K,
             const float* __restrict__ V, float* __restrict__ ctx) {
    extern __shared__ float smf[];
    float* Kst = smf;                      // [2][64][68]
    float* Vst = smf + 2 * KSTG;           // [2][64][72]
    float* Pm  = smf + 2 * KSTG + 2 * VSTG;// [128][68]

    const int tid  = threadIdx.x;
    const int lane = tid & 31;
    const int w    = tid >> 5;
    const int g    = lane >> 2;
    const int tg   = lane & 3;
    const int b    = blockIdx.z;
    const int h    = blockIdx.y;
    const int qrow = blockIdx.x * 128 + w * 16;

    // Q fragments: scale*log2(e) folded in, tf32-rounded
    const float cs = 0.125f * 1.44269504088896340736f;
    unsigned qa[8][4];
    const float* Qb = Q + ((size_t)(b * S + qrow) * D + h * DK);
    #pragma unroll
    for (int ks = 0; ks < 8; ks++) {
        int c = ks * 8 + tg;
        qa[ks][0] = f2tf(Qb[(size_t)g * D + c] * cs);
        qa[ks][1] = f2tf(Qb[(size_t)(g + 8) * D + c] * cs);
        qa[ks][2] = f2tf(Qb[(size_t)g * D + c + 4] * cs);
        qa[ks][3] = f2tf(Qb[(size_t)(g + 8) * D + c + 4] * cs);
    }

    float o[8][4] = {};
    float m0v = -1e30f, m1v = -1e30f, l0 = 0.f, l1 = 0.f;

    const float* Kb = K + ((size_t)b * S * D + h * DK);
    const float* Vb = V + ((size_t)b * S * D + h * DK);
    float* Pr = Pm + (size_t)(w * 16) * PS2;

    // tile loader: 64 rows x 64 floats = 1024 16B-segs each for K and V
    auto issue = [&](int t) {
        float* kd = Kst + (t & 1) * KSTG;
        float* vd = Vst + (t & 1) * VSTG;
        const int rb = t * 64;
        #pragma unroll
        for (int i = 0; i < 4; i++) {
            int sseg = tid + i * 256;
            int r = sseg >> 4, c4 = (sseg & 15) << 2;
            cp16(kd + r * KS2 + c4, Kb + (size_t)(rb + r) * D + c4);
            cp16(vd + r * VS2 + c4, Vb + (size_t)(rb + r) * D + c4);
        }
    };

    issue(0); CP_COMMIT();
    issue(1); CP_COMMIT();

    const int NT = S / 64;   // 32
    for (int t = 0; t < NT; t++) {
        if (t < NT - 1) CP_WAIT1(); else CP_WAIT0();
        __syncthreads();

        const float* Kt = Kst + (t & 1) * KSTG;
        const float* Vt = Vst + (t & 1) * VSTG;

        // S = Q @ K^T (log2-scaled)
        float s[8][4] = {};
        #pragma unroll
        for (int ks = 0; ks < 8; ks++) {
            const int kb = ks * 8;
            #pragma unroll
            for (int nt = 0; nt < 8; nt++) {
                unsigned b0 = __float_as_uint(Kt[(nt * 8 + g) * KS2 + kb + tg]);
                unsigned b1 = __float_as_uint(Kt[(nt * 8 + g) * KS2 + kb + tg + 4]);
                mma_tf32(s[nt], qa[ks][0], qa[ks][1], qa[ks][2], qa[ks][3], b0, b1);
            }
        }

        // online softmax (rows g and g+8)
        float mx0 = -1e30f, mx1 = -1e30f;
        #pragma unroll
        for (int nt = 0; nt < 8; nt++) {
            mx0 = fmaxf(mx0, fmaxf(s[nt][0], s[nt][1]));
            mx1 = fmaxf(mx1, fmaxf(s[nt][2], s[nt][3]));
        }
        mx0 = fmaxf(mx0, __shfl_xor_sync(0xffffffffu, mx0, 1));
        mx0 = fmaxf(mx0, __shfl_xor_sync(0xffffffffu, mx0, 2));
        mx1 = fmaxf(mx1, __shfl_xor_sync(0xffffffffu, mx1, 1));
        mx1 = fmaxf(mx1, __shfl_xor_sync(0xffffffffu, mx1, 2));

        float mn0 = fmaxf(m0v, mx0), mn1 = fmaxf(m1v, mx1);
        float a0 = ex2(m0v - mn0), a1 = ex2(m1v - mn1);
        m0v = mn0; m1v = mn1;
        l0 *= a0; l1 *= a1;
        #pragma unroll
        for (int nt = 0; nt < 8; nt++) {
            o[nt][0] *= a0; o[nt][1] *= a0;
            o[nt][2] *= a1; o[nt][3] *= a1;
        }
        #pragma unroll
        for (int nt = 0; nt < 8; nt++) {
            float p0 = tf32r(ex2(s[nt][0] - mn0));
            float p1 = tf32r(ex2(s[nt][1] - mn0));
            float p2 = tf32r(ex2(s[nt][2] - mn1));
            float p3 = tf32r(ex2(s[nt][3] - mn1));
            l0 += p0 + p1; l1 += p2 + p3;
            int c = nt * 8 + tg * 2;
            *(float2*)&Pr[(size_t)g * PS2 + c]       = make_float2(p0, p1);
            *(float2*)&Pr[(size_t)(g + 8) * PS2 + c] = make_float2(p2, p3);
        }
        __syncwarp();

        // O += P @ V
        #pragma unroll
        for (int ks = 0; ks < 8; ks++) {
            const int kb = ks * 8;
            unsigned pa0 = __float_as_uint(Pr[(size_t)g * PS2 + kb + tg]);
            unsigned pa1 = __float_as_uint(Pr[(size_t)(g + 8) * PS2 + kb + tg]);
            unsigned pa2 = __float_as_uint(Pr[(size_t)g * PS2 + kb + tg + 4]);
            unsigned pa3 = __float_as_uint(Pr[(size_t)(g + 8) * PS2 + kb + tg + 4]);
            #pragma unroll
            for (int nt = 0; nt < 8; nt++) {
                unsigned b0 = __float_as_uint(Vt[(kb + tg) * VS2 + nt * 8 + g]);
                unsigned b1 = __float_as_uint(Vt[(kb + tg + 4) * VS2 + nt * 8 + g]);
                mma_tf32(o[nt], pa0, pa1, pa2, pa3, b0, b1);
            }
        }

        __syncthreads();   // all warps done with stage (t&1) before refill
        if (t + 2 < NT) { issue(t + 2); CP_COMMIT(); }
    }

    l0 += __shfl_xor_sync(0xffffffffu, l0, 1);
    l0 += __shfl_xor_sync(0xffffffffu, l0, 2);
    l1 += __shfl_xor_sync(0xffffffffu, l1, 1);
    l1 += __shfl_xor_sync(0xffffffffu, l1, 2);
    const float i0 = 1.f / l0, i1 = 1.f / l1;

    float* Ob = ctx + ((size_t)(b * S + qrow) * D + h * DK);
    #pragma unroll
    for (int nt = 0; nt < 8; nt++) {
        int c = nt * 8 + tg * 2;
        *(float2*)&Ob[(size_t)g * D + c]       = make_float2(o[nt][0] * i0, o[nt][1] * i0);
        *(float2*)&Ob[(size_t)(g + 8) * D + c] = make_float2(o[nt][2] * i1, o[nt][3] * i1);
    }
}

// ---------------------------------------------------------------------------
// Launch
// ---------------------------------------------------------------------------
extern "C" void kernel_launch(void* const* d_in, const int* in_sizes, int n_in,
                              void* d_out, int out_size) {
    const float* query = (const float*)d_in[0];
    const float* key   = (const float*)d_in[1];
    const float* value = (const float*)d_in[2];
    const float* w_q   = (const float*)d_in[3];
    const float* w_k   = (const float*)d_in[4];
    const float* w_v   = (const float*)d_in[5];
    const float* w_o   = (const float*)d_in[6];
    float* out = (float*)d_out;

    float *Qp, *Kp, *Vp, *Cp;
    __nv_bfloat16 *Ahp, *Alp, *Whp, *Wlp;
    cudaGetSymbolAddress((void**)&Qp,  g_Q);
    cudaGetSymbolAddress((void**)&Kp,  g_K);
    cudaGetSymbolAddress((void**)&Vp,  g_V);
    cudaGetSymbolAddress((void**)&Cp,  g_C);
    cudaGetSymbolAddress((void**)&Ahp, g_Ah);
    cudaGetSymbolAddress((void**)&Alp, g_Al);
    cudaGetSymbolAddress((void**)&Whp, g_Wh);
    cudaGetSymbolAddress((void**)&Wlp, g_Wl);

    const int M = B * S;                  // 4096
    dim3 ggrid(D / 128, M / 128);         // (8, 32)
    const int act4 = M * D / 4;
    const int wgt4 = D * D / 4;

    const int smem_gemm = 2 * 4 * ASZ * (int)sizeof(__nv_bfloat16);  // 81920
    cudaFuncSetAttribute(gemm_bf16x3, cudaFuncAttributeMaxDynamicSharedMemorySize, smem_gemm);

    // Q/K/V projections (outputs tf32-rounded for the attention kernel)
    split_bf16<<<(wgt4 + 255) / 256, 256>>>(w_q,   Whp, Wlp, wgt4);
    split_bf16<<<(act4 + 255) / 256, 256>>>(query, Ahp, Alp, act4);
    gemm_bf16x3<<<ggrid, 256, smem_gemm>>>(Ahp, Alp, Whp, Wlp, Qp, M, D, D, 1);

    split_bf16<<<(wgt4 + 255) / 256, 256>>>(w_k, Whp, Wlp, wgt4);
    split_bf16<<<(act4 + 255) / 256, 256>>>(key, Ahp, Alp, act4);
    gemm_bf16x3<<<ggrid, 256, smem_gemm>>>(Ahp, Alp, Whp, Wlp, Kp, M, D, D, 1);

    split_bf16<<<(wgt4 + 255) / 256, 256>>>(w_v,   Whp, Wlp, wgt4);
    split_bf16<<<(act4 + 255) / 256, 256>>>(value, Ahp, Alp, act4);
    gemm_bf16x3<<<ggrid, 256, smem_gemm>>>(Ahp, Alp, Whp, Wlp, Vp, M, D, D, 1);

    // attention
    cudaFuncSetAttribute(attn_tc, cudaFuncAttributeMaxDynamicSharedMemorySize, A_SMEM);
    dim3 agrid(S / 128, H, B);            // (16, 16, 2)
    attn_tc<<<agrid, 256, A_SMEM>>>(Qp, Kp, Vp, Cp);

    // output projection (full fp32 output)
    split_bf16<<<(wgt4 + 255) / 256, 256>>>(w_o, Whp, Wlp, wgt4);
    split_bf16<<<(act4 + 255) / 256, 256>>>(Cp,  Ahp, Alp, act4);
    gemm_bf16x3<<<ggrid, 256, smem_gemm>>>(Ahp, Alp, Whp, Wlp, out, M, D, D, 0);
}